// round 14
// baseline (speedup 1.0000x reference)
#include <cuda_runtime.h>
#include <stdint.h>

// adjacency_full[i, neighbor_indices[i, j]] = adjacency_values[i, j]
// N = 8192, K = 64. Output: N*N fp32 (256 MB).
//
// R13 with split-half early TMA issue. One CTA per row, 32KB smem row built
// in two 16KB halves; the bulk store for the lower half is issued as soon as
// that half is zeroed+scattered, overlapping its DRAM drain with the upper
// half's build. Scatter is predicated per half (no divergent loops).

#define N_PATCHES 8192
#define K_NEIGH   64
#define THREADS   128
#define HALF      (N_PATCHES / 2)          // 4096 columns
#define HALF_BYTES (HALF * 4)              // 16 KB
#define HALF_V4   (HALF / 4)               // 1024 float4
#define PER_THR   (HALF_V4 / THREADS)      // 8 float4 per thread per half

__global__ void __launch_bounds__(THREADS)
tma_split_row_kernel(const float* __restrict__ vals,
                     const int*   __restrict__ idx,
                     float* __restrict__ out)
{
    __shared__ __align__(128) float row[N_PATCHES];   // 32 KB
    const int r   = blockIdx.x;
    const int tid = threadIdx.x;

    // Phase 0: prefetch scatter operands (hidden under the zero-fill).
    int   c = 0;
    float v = 0.f;
    if (tid < K_NEIGH) {
        int t = r * K_NEIGH + tid;
        c = idx[t];
        v = vals[t];
    }

    float4* row4 = reinterpret_cast<float4*>(row);
    const float4 z4 = make_float4(0.f, 0.f, 0.f, 0.f);
    float* dst = out + (size_t)r * N_PATCHES;

    uint32_t saddr;
    asm("{ .reg .u64 t; cvta.to.shared.u64 t, %1; cvt.u32.u64 %0, t; }"
        : "=r"(saddr) : "l"(row));

    // ---- Lower half: build then issue its 16KB bulk store immediately ----
    #pragma unroll
    for (int j = 0; j < PER_THR; j++)
        row4[tid + j * THREADS] = z4;
    __syncthreads();
    if (tid < K_NEIGH && c < HALF)
        row[c] = v;
    __syncthreads();
    asm volatile("fence.proxy.async.shared::cta;" ::: "memory");
    if (tid == 0) {
        asm volatile(
            "cp.async.bulk.global.shared::cta.bulk_group [%0], [%1], %2;"
            :: "l"(dst), "r"(saddr), "n"(HALF_BYTES) : "memory");
        asm volatile("cp.async.bulk.commit_group;" ::: "memory");
    }

    // ---- Upper half: build (overlaps lower half's drain), then issue ----
    #pragma unroll
    for (int j = 0; j < PER_THR; j++)
        row4[HALF_V4 + tid + j * THREADS] = z4;
    __syncthreads();
    if (tid < K_NEIGH && c >= HALF)
        row[c] = v;
    __syncthreads();
    asm volatile("fence.proxy.async.shared::cta;" ::: "memory");
    if (tid == 0) {
        asm volatile(
            "cp.async.bulk.global.shared::cta.bulk_group [%0], [%1], %2;"
            :: "l"(dst + HALF), "r"(saddr + HALF_BYTES), "n"(HALF_BYTES)
            : "memory");
        asm volatile("cp.async.bulk.commit_group;" ::: "memory");
        // smem must remain allocated until both bulk stores have read it.
        asm volatile("cp.async.bulk.wait_group 0;" ::: "memory");
    }
}

extern "C" void kernel_launch(void* const* d_in, const int* in_sizes, int n_in,
                              void* d_out, int out_size)
{
    const float* vals = (const float*)d_in[0];   // [N, K] float32
    const int*   idx  = (const int*)  d_in[1];   // [N, K] int32
    float* out = (float*)d_out;                  // [N, N] float32

    tma_split_row_kernel<<<N_PATCHES, THREADS, 0, 0>>>(vals, idx, out);
}

// round 15
// speedup vs baseline: 1.0177x; 1.0177x over previous
#include <cuda_runtime.h>
#include <stdint.h>

// adjacency_full[i, neighbor_indices[i, j]] = adjacency_values[i, j]
// N = 8192, K = 64. Output: N*N fp32 (256 MB).
//
// Quarter-split TMA streamer (R14 refined). One CTA per row; the 32KB smem
// row is built and shipped in four 8KB quarters, each cp.async.bulk issued
// as soon as its quarter is zeroed+scattered. The DRAM drain of quarter q
// overlaps the smem build of quarter q+1; the serialized prefix is only 8KB.

#define N_PATCHES 8192
#define K_NEIGH   64
#define THREADS   128
#define QUARTER     (N_PATCHES / 4)        // 2048 columns
#define Q_BYTES     (QUARTER * 4)          // 8 KB
#define Q_V4        (QUARTER / 4)          // 512 float4
#define PER_THR     (Q_V4 / THREADS)       // 4 float4 per thread per quarter

__global__ void __launch_bounds__(THREADS)
tma_quarter_row_kernel(const float* __restrict__ vals,
                       const int*   __restrict__ idx,
                       float* __restrict__ out)
{
    __shared__ __align__(128) float row[N_PATCHES];   // 32 KB
    const int r   = blockIdx.x;
    const int tid = threadIdx.x;

    // Prefetch scatter operands (latency hides under the first zero-fill).
    int   c = 0;
    float v = 0.f;
    if (tid < K_NEIGH) {
        int t = r * K_NEIGH + tid;
        c = idx[t];
        v = vals[t];
    }

    float4* row4 = reinterpret_cast<float4*>(row);
    const float4 z4 = make_float4(0.f, 0.f, 0.f, 0.f);
    float* dst = out + (size_t)r * N_PATCHES;

    uint32_t saddr;
    asm("{ .reg .u64 t; cvta.to.shared.u64 t, %1; cvt.u32.u64 %0, t; }"
        : "=r"(saddr) : "l"(row));

    #pragma unroll
    for (int q = 0; q < 4; q++) {
        const int base_v4 = q * Q_V4;
        const int lo      = q * QUARTER;

        // Build quarter q: zero fill (4 STS.128/thread) ...
        #pragma unroll
        for (int j = 0; j < PER_THR; j++)
            row4[base_v4 + tid + j * THREADS] = z4;
        __syncthreads();
        // ... plus predicated scatter of this quarter's values.
        if (tid < K_NEIGH && (unsigned)(c - lo) < (unsigned)QUARTER)
            row[c] = v;
        __syncthreads();

        // Ship it: 8KB bulk store, fire-and-forget (drain overlaps q+1 build).
        asm volatile("fence.proxy.async.shared::cta;" ::: "memory");
        if (tid == 0) {
            asm volatile(
                "cp.async.bulk.global.shared::cta.bulk_group [%0], [%1], %2;"
                :: "l"(dst + lo), "r"(saddr + q * Q_BYTES), "n"(Q_BYTES)
                : "memory");
            asm volatile("cp.async.bulk.commit_group;" ::: "memory");
        }
    }

    // smem must remain allocated until all four bulk stores have read it.
    if (tid == 0)
        asm volatile("cp.async.bulk.wait_group 0;" ::: "memory");
}

extern "C" void kernel_launch(void* const* d_in, const int* in_sizes, int n_in,
                              void* d_out, int out_size)
{
    const float* vals = (const float*)d_in[0];   // [N, K] float32
    const int*   idx  = (const int*)  d_in[1];   // [N, K] int32
    float* out = (float*)d_out;                  // [N, N] float32

    tma_quarter_row_kernel<<<N_PATCHES, THREADS, 0, 0>>>(vals, idx, out);
}